// round 1
// baseline (speedup 1.0000x reference)
#include <cuda_runtime.h>

#define Bb 8
#define Tt 12
#define Nn 307
#define NP 308          // padded row length for float4-aligned scratch
#define Cc 64
#define BT 96           // B*T

// global scratch (allocation-free: __device__ arrays)
__device__ float g_QT[BT * Cc * NP];   // Q^T per (b,t): [e][m], pre-scaled by 1/sqrt(8)
__device__ float g_KT[BT * Cc * NP];   // K^T per (b,t): [e][m]

// ---------------- Kernel A: Q/K projection ----------------
// x is [B, C, T, N] so for fixed (b,t) the slice x[c][n] is n-contiguous:
// projection is a 64x64 @ 64x307 GEMM producing Q^T/K^T directly.
#define MT_A 80
#define A_SMEM_FLOATS (Cc*MT_A + 2*Cc*Cc)   // 13312 floats = 53248 B

__global__ void __launch_bounds__(160, 3)
proj_kernel(const float* __restrict__ x,
            const float* __restrict__ Wq, const float* __restrict__ bq,
            const float* __restrict__ Wk, const float* __restrict__ bk)
{
    extern __shared__ float sm[];
    float (*xs)[MT_A] = (float(*)[MT_A])sm;                       // [c][m]
    float (*wqs)[Cc]  = (float(*)[Cc])(sm + Cc*MT_A);             // [c][e]
    float (*wks)[Cc]  = (float(*)[Cc])(sm + Cc*MT_A + Cc*Cc);     // [c][e]

    int bt = blockIdx.x, b = bt / Tt, t = bt % Tt;
    int m0 = blockIdx.y * MT_A;
    int mlen = Nn - m0; if (mlen > MT_A) mlen = MT_A;
    int tid = threadIdx.y * 10 + threadIdx.x;   // blockDim = (10,16) = 160

    // load W transposed into smem: wqs[c][e] = Wq[e][c]
    for (int i = tid; i < Cc*Cc; i += 160) {
        int c = i >> 6, e = i & 63;
        wqs[c][e] = Wq[e*Cc + c];
        wks[c][e] = Wk[e*Cc + c];
    }
    // load x slice (already [c][m] contiguous in m)
    const float* xbase = x + ((b*Cc)*Tt + t)*Nn + m0;
    for (int i = tid; i < Cc*MT_A; i += 160) {
        int c = i / MT_A, m = i % MT_A;
        xs[c][m] = (m < mlen) ? xbase[c*(Tt*Nn) + m] : 0.f;
    }
    __syncthreads();

    int e0 = threadIdx.y * 4;       // 4 e per thread
    int mm = threadIdx.x * 8;       // 8 m per thread
    float aq[4][8] = {}, ak[4][8] = {};

    #pragma unroll 4
    for (int c = 0; c < Cc; c++) {
        float4 wq4 = *(const float4*)&wqs[c][e0];
        float4 wk4 = *(const float4*)&wks[c][e0];
        float4 xa  = *(const float4*)&xs[c][mm];
        float4 xb4 = *(const float4*)&xs[c][mm+4];
        float xv[8] = {xa.x,xa.y,xa.z,xa.w,xb4.x,xb4.y,xb4.z,xb4.w};
        float wq[4] = {wq4.x,wq4.y,wq4.z,wq4.w};
        float wk[4] = {wk4.x,wk4.y,wk4.z,wk4.w};
        #pragma unroll
        for (int i2 = 0; i2 < 4; i2++)
            #pragma unroll
            for (int j = 0; j < 8; j++) {
                aq[i2][j] += wq[i2]*xv[j];
                ak[i2][j] += wk[i2]*xv[j];
            }
    }

    const float scale = 0.35355339059327373f;   // 1/sqrt(DK=8)
    #pragma unroll
    for (int i2 = 0; i2 < 4; i2++) {
        float bqv = bq[e0+i2], bkv = bk[e0+i2];
        int base = (bt*Cc + e0+i2)*NP + m0 + mm;
        #pragma unroll
        for (int j = 0; j < 8; j++) {
            if (m0 + mm + j < Nn) {
                g_QT[base+j] = (aq[i2][j] + bqv) * scale;
                g_KT[base+j] =  ak[i2][j] + bkv;
            }
        }
    }
}

// ---------------- Kernel B: scores + mask + softmax ----------------
// grid (96, 5): one block per (b,t, 64-row tile). threads (40,8)=320,
// thread tile 8 rows x 8 cols, K^T tile (64x320) + Q^T tile (64x64) in smem.
#define B_SMEM_FLOATS (Cc*320 + Cc*64)   // 24576 floats = 98304 B

__global__ void __launch_bounds__(320, 2)
attn_kernel(const int* __restrict__ mask, float* __restrict__ out)
{
    extern __shared__ float sm[];
    float (*KT)[320] = (float(*)[320])sm;            // [c][m]
    float (*QT)[64]  = (float(*)[64])(sm + Cc*320);  // [c][r]

    int bt = blockIdx.x, b = bt / Tt;
    int r0 = blockIdx.y * 64;
    int rows = Nn - r0; if (rows > 64) rows = 64;
    int tid = threadIdx.y * 40 + threadIdx.x;        // blockDim (40,8) = 320

    // load K^T tile (m padded to 320 with zeros)
    for (int i = tid; i < Cc*80; i += 320) {
        int c = i / 80, m4 = (i % 80) * 4;
        float4 v = make_float4(0.f, 0.f, 0.f, 0.f);
        if (m4 < NP) v = *(const float4*)&g_KT[(bt*Cc + c)*NP + m4];
        *(float4*)&KT[c][m4] = v;
    }
    // load Q^T tile for this row range
    for (int i = tid; i < Cc*64; i += 320) {
        int c = i >> 6, r = i & 63;
        QT[c][r] = (r < rows) ? g_QT[(bt*Cc + c)*NP + r0 + r] : 0.f;
    }
    __syncthreads();

    float acc[8][8] = {};
    int rr = threadIdx.y * 8, mm = threadIdx.x * 8;

    #pragma unroll 4
    for (int c = 0; c < Cc; c++) {
        float4 q0 = *(const float4*)&QT[c][rr];
        float4 q1 = *(const float4*)&QT[c][rr+4];
        float4 k0 = *(const float4*)&KT[c][mm];
        float4 k1 = *(const float4*)&KT[c][mm+4];
        float qv[8] = {q0.x,q0.y,q0.z,q0.w,q1.x,q1.y,q1.z,q1.w};
        float kv[8] = {k0.x,k0.y,k0.z,k0.w,k1.x,k1.y,k1.z,k1.w};
        #pragma unroll
        for (int i2 = 0; i2 < 8; i2++)
            #pragma unroll
            for (int j = 0; j < 8; j++)
                acc[i2][j] += qv[i2]*kv[j];
    }
    __syncthreads();   // done reading KT/QT

    // spill scores into smem (reuse KT region): S[r][m], r<64, m<320
    float* S = sm;
    #pragma unroll
    for (int i2 = 0; i2 < 8; i2++) {
        #pragma unroll
        for (int j = 0; j < 8; j += 4) {
            float4 v = make_float4(acc[i2][j], acc[i2][j+1], acc[i2][j+2], acc[i2][j+3]);
            *(float4*)&S[(rr+i2)*320 + mm + j] = v;
        }
    }
    __syncthreads();

    // softmax: one warp per row (10 warps), fully unrolled register-resident row
    int wid = tid >> 5, lane = tid & 31;
    for (int r = wid; r < rows; r += 10) {
        int n = r0 + r;
        const int* mrow = mask + (b*Nn + n)*Nn;
        float v[10];
        float mx = -3.4e38f;
        #pragma unroll
        for (int it = 0; it < 10; it++) {
            int m = lane + it*32;
            float s = -3.4e38f;
            if (m < Nn) s = mrow[m] ? S[r*320 + m] : -1e9f;
            v[it] = s;
            mx = fmaxf(mx, s);
        }
        #pragma unroll
        for (int o = 16; o; o >>= 1)
            mx = fmaxf(mx, __shfl_xor_sync(0xffffffffu, mx, o));

        float ssum = 0.f;
        #pragma unroll
        for (int it = 0; it < 10; it++) {
            float e = __expf(v[it] - mx);   // inactive lanes underflow to 0
            v[it] = e;
            ssum += e;
        }
        #pragma unroll
        for (int o = 16; o; o >>= 1)
            ssum += __shfl_xor_sync(0xffffffffu, ssum, o);

        float inv = 1.0f / ssum;
        float* orow = out + ((size_t)(bt*Nn + n)) * Nn;
        #pragma unroll
        for (int it = 0; it < 10; it++) {
            int m = lane + it*32;
            if (m < Nn) orow[m] = v[it] * inv;
        }
    }
}

extern "C" void kernel_launch(void* const* d_in, const int* in_sizes, int n_in,
                              void* d_out, int out_size)
{
    const float* x    = (const float*)d_in[0];
    const int*   mask = (const int*)  d_in[1];
    const float* Wq   = (const float*)d_in[2];
    const float* bq   = (const float*)d_in[3];
    const float* Wk   = (const float*)d_in[4];
    const float* bk   = (const float*)d_in[5];
    float* out = (float*)d_out;

    cudaFuncSetAttribute(proj_kernel, cudaFuncAttributeMaxDynamicSharedMemorySize,
                         A_SMEM_FLOATS * (int)sizeof(float));
    cudaFuncSetAttribute(attn_kernel, cudaFuncAttributeMaxDynamicSharedMemorySize,
                         B_SMEM_FLOATS * (int)sizeof(float));

    proj_kernel<<<dim3(BT, 4), dim3(10, 16), A_SMEM_FLOATS * sizeof(float)>>>(x, Wq, bq, Wk, bk);
    attn_kernel<<<dim3(BT, 5), dim3(40, 8), B_SMEM_FLOATS * sizeof(float)>>>(mask, out);
}

// round 2
// speedup vs baseline: 1.0203x; 1.0203x over previous
#include <cuda_runtime.h>

#define Bb 8
#define Tt 12
#define Nn 307
#define NP 308
#define Cc 64
#define BT 96

__device__ float g_QT[BT * Cc * NP];   // Q^T per (b,t): [e][m], pre-scaled by 1/sqrt(8)
__device__ float g_KT[BT * Cc * NP];   // K^T per (b,t): [e][m]

// ---- packed f32x2 helpers (sm_103a) ----
#define FMA2(d, a, b) asm("fma.rn.f32x2 %0, %1, %2, %0;" : "+l"(d) : "l"(a), "l"(b))
#define PACK2(d, lo, hi) asm("mov.b64 %0, {%1, %2};" : "=l"(d) : "f"(lo), "f"(hi))
#define UNPACK2(lo, hi, d) asm("mov.b64 {%0, %1}, %2;" : "=f"(lo), "=f"(hi) : "l"(d))

// ---------------- Kernel A: Q/K projection ----------------
#define MT_A 80
#define A_SMEM_FLOATS (Cc*MT_A + 2*Cc*Cc)

__global__ void __launch_bounds__(160, 3)
proj_kernel(const float* __restrict__ x,
            const float* __restrict__ Wq, const float* __restrict__ bq,
            const float* __restrict__ Wk, const float* __restrict__ bk)
{
    extern __shared__ float sm[];
    float (*xs)[MT_A] = (float(*)[MT_A])sm;
    float (*wqs)[Cc]  = (float(*)[Cc])(sm + Cc*MT_A);
    float (*wks)[Cc]  = (float(*)[Cc])(sm + Cc*MT_A + Cc*Cc);

    int bt = blockIdx.x, b = bt / Tt, t = bt % Tt;
    int m0 = blockIdx.y * MT_A;
    int mlen = Nn - m0; if (mlen > MT_A) mlen = MT_A;
    int tid = threadIdx.y * 10 + threadIdx.x;

    for (int i = tid; i < Cc*Cc; i += 160) {
        int c = i >> 6, e = i & 63;
        wqs[c][e] = Wq[e*Cc + c];
        wks[c][e] = Wk[e*Cc + c];
    }
    const float* xbase = x + ((b*Cc)*Tt + t)*Nn + m0;
    for (int i = tid; i < Cc*MT_A; i += 160) {
        int c = i / MT_A, m = i % MT_A;
        xs[c][m] = (m < mlen) ? xbase[c*(Tt*Nn) + m] : 0.f;
    }
    __syncthreads();

    int e0 = threadIdx.y * 4;       // 4 e per thread (2 e-pairs)
    int mm = threadIdx.x * 8;       // 8 m per thread

    // acc2[p][j]: lo = e0+2p, hi = e0+2p+1, col mm+j
    unsigned long long aq2[2][8], ak2[2][8];
    #pragma unroll
    for (int p = 0; p < 2; p++)
        #pragma unroll
        for (int j = 0; j < 8; j++) { aq2[p][j] = 0ull; ak2[p][j] = 0ull; }

    #pragma unroll 4
    for (int c = 0; c < Cc; c++) {
        float4 wq4 = *(const float4*)&wqs[c][e0];
        float4 wk4 = *(const float4*)&wks[c][e0];
        float4 xa  = *(const float4*)&xs[c][mm];
        float4 xb4 = *(const float4*)&xs[c][mm+4];
        unsigned long long qp[2], kp[2], xd[8];
        PACK2(qp[0], wq4.x, wq4.y); PACK2(qp[1], wq4.z, wq4.w);
        PACK2(kp[0], wk4.x, wk4.y); PACK2(kp[1], wk4.z, wk4.w);
        float xv[8] = {xa.x,xa.y,xa.z,xa.w,xb4.x,xb4.y,xb4.z,xb4.w};
        #pragma unroll
        for (int j = 0; j < 8; j++) PACK2(xd[j], xv[j], xv[j]);
        #pragma unroll
        for (int p = 0; p < 2; p++)
            #pragma unroll
            for (int j = 0; j < 8; j++) {
                FMA2(aq2[p][j], qp[p], xd[j]);
                FMA2(ak2[p][j], kp[p], xd[j]);
            }
    }

    const float scale = 0.35355339059327373f;   // 1/sqrt(DK=8)
    #pragma unroll
    for (int p = 0; p < 2; p++) {
        #pragma unroll
        for (int h = 0; h < 2; h++) {
            int e = e0 + 2*p + h;
            float bqv = bq[e], bkv = bk[e];
            int base = (bt*Cc + e)*NP + m0 + mm;
            #pragma unroll
            for (int j = 0; j < 8; j++) {
                float qlo, qhi, klo, khi;
                UNPACK2(qlo, qhi, aq2[p][j]);
                UNPACK2(klo, khi, ak2[p][j]);
                float qv = h ? qhi : qlo;
                float kv = h ? khi : klo;
                if (m0 + mm + j < Nn) {
                    g_QT[base+j] = (qv + bqv) * scale;
                    g_KT[base+j] =  kv + bkv;
                }
            }
        }
    }
}

// ---------------- Kernel B: scores + mask + softmax ----------------
#define B_SMEM_FLOATS (Cc*320 + Cc*64)

__global__ void __launch_bounds__(320, 2)
attn_kernel(const int* __restrict__ mask, float* __restrict__ out)
{
    extern __shared__ float sm[];
    float (*KT)[320] = (float(*)[320])sm;
    float (*QT)[64]  = (float(*)[64])(sm + Cc*320);

    int bt = blockIdx.x, b = bt / Tt;
    int r0 = blockIdx.y * 64;
    int rows = Nn - r0; if (rows > 64) rows = 64;
    int tid = threadIdx.y * 40 + threadIdx.x;

    for (int i = tid; i < Cc*80; i += 320) {
        int c = i / 80, m4 = (i % 80) * 4;
        float4 v = make_float4(0.f, 0.f, 0.f, 0.f);
        if (m4 < NP) v = *(const float4*)&g_KT[(bt*Cc + c)*NP + m4];
        *(float4*)&KT[c][m4] = v;
    }
    for (int i = tid; i < Cc*64; i += 320) {
        int c = i >> 6, r = i & 63;
        QT[c][r] = (r < rows) ? g_QT[(bt*Cc + c)*NP + r0 + r] : 0.f;
    }
    __syncthreads();

    int rr = threadIdx.y * 8, mm = threadIdx.x * 8;

    // acc2[p][j]: lo = row rr+2p, hi = row rr+2p+1, col mm+j
    unsigned long long acc2[4][8];
    #pragma unroll
    for (int p = 0; p < 4; p++)
        #pragma unroll
        for (int j = 0; j < 8; j++) acc2[p][j] = 0ull;

    #pragma unroll 4
    for (int c = 0; c < Cc; c++) {
        float4 q0 = *(const float4*)&QT[c][rr];
        float4 q1 = *(const float4*)&QT[c][rr+4];
        float4 k0 = *(const float4*)&KT[c][mm];
        float4 k1 = *(const float4*)&KT[c][mm+4];
        unsigned long long qp[4], kd[8];
        PACK2(qp[0], q0.x, q0.y); PACK2(qp[1], q0.z, q0.w);
        PACK2(qp[2], q1.x, q1.y); PACK2(qp[3], q1.z, q1.w);
        float kv[8] = {k0.x,k0.y,k0.z,k0.w,k1.x,k1.y,k1.z,k1.w};
        #pragma unroll
        for (int j = 0; j < 8; j++) PACK2(kd[j], kv[j], kv[j]);
        #pragma unroll
        for (int p = 0; p < 4; p++)
            #pragma unroll
            for (int j = 0; j < 8; j++)
                FMA2(acc2[p][j], qp[p], kd[j]);
    }
    __syncthreads();

    // spill scores into smem (reuse KT region): S[r][m]
    float* S = sm;
    #pragma unroll
    for (int p = 0; p < 4; p++) {
        float lo[8], hi[8];
        #pragma unroll
        for (int j = 0; j < 8; j++) UNPACK2(lo[j], hi[j], acc2[p][j]);
        #pragma unroll
        for (int j = 0; j < 8; j += 4) {
            *(float4*)&S[(rr+2*p  )*320 + mm + j] = make_float4(lo[j],lo[j+1],lo[j+2],lo[j+3]);
            *(float4*)&S[(rr+2*p+1)*320 + mm + j] = make_float4(hi[j],hi[j+1],hi[j+2],hi[j+3]);
        }
    }
    __syncthreads();

    // softmax: one warp per row
    int wid = tid >> 5, lane = tid & 31;
    for (int r = wid; r < rows; r += 10) {
        int n = r0 + r;
        const int* mrow = mask + (b*Nn + n)*Nn;
        float v[10];
        float mx = -3.4e38f;
        #pragma unroll
        for (int it = 0; it < 10; it++) {
            int m = lane + it*32;
            float s = -3.4e38f;
            if (m < Nn) s = mrow[m] ? S[r*320 + m] : -1e9f;
            v[it] = s;
            mx = fmaxf(mx, s);
        }
        #pragma unroll
        for (int o = 16; o; o >>= 1)
            mx = fmaxf(mx, __shfl_xor_sync(0xffffffffu, mx, o));

        float ssum = 0.f;
        #pragma unroll
        for (int it = 0; it < 10; it++) {
            float e = __expf(v[it] - mx);
            v[it] = e;
            ssum += e;
        }
        #pragma unroll
        for (int o = 16; o; o >>= 1)
            ssum += __shfl_xor_sync(0xffffffffu, ssum, o);

        float inv = 1.0f / ssum;
        float* orow = out + ((size_t)(bt*Nn + n)) * Nn;
        #pragma unroll
        for (int it = 0; it < 10; it++) {
            int m = lane + it*32;
            if (m < Nn) orow[m] = v[it] * inv;
        }
    }
}

extern "C" void kernel_launch(void* const* d_in, const int* in_sizes, int n_in,
                              void* d_out, int out_size)
{
    const float* x    = (const float*)d_in[0];
    const int*   mask = (const int*)  d_in[1];
    const float* Wq   = (const float*)d_in[2];
    const float* bq   = (const float*)d_in[3];
    const float* Wk   = (const float*)d_in[4];
    const float* bk   = (const float*)d_in[5];
    float* out = (float*)d_out;

    cudaFuncSetAttribute(proj_kernel, cudaFuncAttributeMaxDynamicSharedMemorySize,
                         A_SMEM_FLOATS * (int)sizeof(float));
    cudaFuncSetAttribute(attn_kernel, cudaFuncAttributeMaxDynamicSharedMemorySize,
                         B_SMEM_FLOATS * (int)sizeof(float));

    proj_kernel<<<dim3(BT, 4), dim3(10, 16), A_SMEM_FLOATS * sizeof(float)>>>(x, Wq, bq, Wk, bk);
    attn_kernel<<<dim3(BT, 5), dim3(40, 8), B_SMEM_FLOATS * sizeof(float)>>>(mask, out);
}